// round 11
// baseline (speedup 1.0000x reference)
#include <cuda_runtime.h>
#include <cuda_bf16.h>
#include <cuda_fp16.h>
#include <mma.h>
#include <cstdint>

using namespace nvcuda;

#define NN 50000
#define NE 800000
#define H  64
#define REL 5
#define NB 196          // (NN + 255) / 256

// ---- device scratch (static globals; no runtime allocation) ----
__device__ unsigned int g_zh[NN * 32];           // z as half2   (6.4 MB)
__device__ unsigned int g_yh[REL * NN * 32];     // y_r as half2 (32 MB)
__device__ float g_m[NN * H];            // fused message (edge-pass output)
__device__ int   g_deg[NN];              // col-degree (for gcn norm)
__device__ int   g_cnt[NN];              // row-degree (for sort)
__device__ int   g_off[NN + 1];          // CSR offsets by dst
__device__ int   g_cur[NN];              // scatter cursors
__device__ int   g_es[NE];               // sorted packed edges: src | type<<16
__device__ int   g_bsum[NB];             // per-block sums for scan
__device__ __nv_bfloat16 g_Ah[NN * H];   // risk hi split (6.4 MB)
__device__ __nv_bfloat16 g_Al[NN * H];   // risk lo split
__device__ __nv_bfloat16 g_Wh[6 * H * H];// combined weights hi split
__device__ __nv_bfloat16 g_Wl[6 * H * H];// combined weights lo split
__device__ float g_BC[6 * H];            // [b | b@W_rel_r]

// ================= prep: zero counters + bf16-split A =================
__global__ void k_prep(const float* __restrict__ risk) {
    int i = blockIdx.x * blockDim.x + threadIdx.x;
    int stride = gridDim.x * blockDim.x;
    for (int j = i; j < NN; j += stride) { g_deg[j] = 0; g_cnt[j] = 0; }
    for (int j = i; j < NN * 16; j += stride) {
        float4 v = ((const float4*)risk)[j];
        __nv_bfloat16 hx = __float2bfloat16(v.x), hy = __float2bfloat16(v.y);
        __nv_bfloat16 hz = __float2bfloat16(v.z), hw = __float2bfloat16(v.w);
        ((__nv_bfloat162*)g_Ah)[j * 2]     = __nv_bfloat162(hx, hy);
        ((__nv_bfloat162*)g_Ah)[j * 2 + 1] = __nv_bfloat162(hz, hw);
        ((__nv_bfloat162*)g_Al)[j * 2]     = __nv_bfloat162(
            __float2bfloat16(v.x - __bfloat162float(hx)),
            __float2bfloat16(v.y - __bfloat162float(hy)));
        ((__nv_bfloat162*)g_Al)[j * 2 + 1] = __nv_bfloat162(
            __float2bfloat16(v.z - __bfloat162float(hz)),
            __float2bfloat16(v.w - __bfloat162float(hw)));
    }
}

// Combined weights (bf16 hi/lo): W[0]=W_in, W[1+r]=W_in@W_rel[r]; BC likewise.
__global__ void k_wcomb(const float* __restrict__ Win, const float* __restrict__ bin,
                        const float* __restrict__ Wrel) {
    int idx = blockIdx.x * blockDim.x + threadIdx.x;
    if (idx >= 6 * H * H) return;
    int m = idx >> 12, k = (idx >> 6) & 63, h = idx & 63;
    float s;
    if (m == 0) {
        s = Win[k * H + h];
        if (k == 0) g_BC[h] = bin[h];
    } else {
        const float* Wr = Wrel + (m - 1) * H * H;
        s = 0.f;
        #pragma unroll 8
        for (int j = 0; j < H; j++) s += Win[k * H + j] * Wr[j * H + h];
        if (k == 0) {
            float sb = 0.f;
            for (int j = 0; j < H; j++) sb += bin[j] * Wr[j * H + h];
            g_BC[m * H + h] = sb;
        }
    }
    __nv_bfloat16 hi = __float2bfloat16(s);
    g_Wh[idx] = hi;
    g_Wl[idx] = __float2bfloat16(s - __bfloat162float(hi));
}

__global__ void k_deg(const int* __restrict__ ei) {
    int e = blockIdx.x * blockDim.x + threadIdx.x;
    if (e < NE) {
        atomicAdd(&g_deg[ei[NE + e]], 1);   // col-degree (norm)
        atomicAdd(&g_cnt[ei[e]], 1);        // row-degree (sort)
    }
}

// ================= tensor-core node GEMM (wmma bf16 split-3) =================
// Grid (391, 6): block = (node-tile of 128, matrix m). 4 warps; warp w owns 32 rows
// (2 M-fragments) -> 48 fragment loads per 96 MMAs instead of 40/48.
#define LDAB 72      // bf16 leading dim (mult of 8 elems = 16B)
#define LDST 68      // float leading dim for staging
#define TCN_SMEM (2 * 128 * LDAB * 2 + 2 * 64 * LDAB * 2)   // 55296 B

__global__ void __launch_bounds__(128) k_node_tc() {
    extern __shared__ char smc[];
    __nv_bfloat16* sAh = (__nv_bfloat16*)smc;
    __nv_bfloat16* sAl = sAh + 128 * LDAB;
    __nv_bfloat16* sWh = sAl + 128 * LDAB;
    __nv_bfloat16* sWl = sWh + 64 * LDAB;
    float*         sSt = (float*)smc;      // staging reuses A region (34.8KB < 36.9KB)

    int t = threadIdx.x;
    int w = t >> 5, lane = t & 31;
    int node0 = blockIdx.x * 128;
    int m = blockIdx.y;

    // fill A tile (bf162 copies; guard tail tile)
    for (int i = t; i < 128 * 32; i += 128) {
        int r = i >> 5, c2 = i & 31;
        int n = node0 + r;
        __nv_bfloat162 vh = __nv_bfloat162(__float2bfloat16(0.f), __float2bfloat16(0.f));
        __nv_bfloat162 vl = vh;
        if (n < NN) {
            vh = ((const __nv_bfloat162*)g_Ah)[n * 32 + c2];
            vl = ((const __nv_bfloat162*)g_Al)[n * 32 + c2];
        }
        ((__nv_bfloat162*)(sAh + r * LDAB))[c2] = vh;
        ((__nv_bfloat162*)(sAl + r * LDAB))[c2] = vl;
    }
    // fill W tile
    for (int i = t; i < 64 * 32; i += 128) {
        int r = i >> 5, c2 = i & 31;
        ((__nv_bfloat162*)(sWh + r * LDAB))[c2] = ((const __nv_bfloat162*)g_Wh)[m * 2048 + i];
        ((__nv_bfloat162*)(sWl + r * LDAB))[c2] = ((const __nv_bfloat162*)g_Wl)[m * 2048 + i];
    }
    __syncthreads();

    wmma::fragment<wmma::accumulator, 16, 16, 16, float> acc[2][4];
    #pragma unroll
    for (int mi = 0; mi < 2; mi++)
        #pragma unroll
        for (int n = 0; n < 4; n++) wmma::fill_fragment(acc[mi][n], 0.f);

    int row0 = w * 32;
    #pragma unroll
    for (int k = 0; k < 4; k++) {
        wmma::fragment<wmma::matrix_a, 16, 16, 16, __nv_bfloat16, wmma::row_major> ah0, al0, ah1, al1;
        wmma::load_matrix_sync(ah0, &sAh[(row0     ) * LDAB + k * 16], LDAB);
        wmma::load_matrix_sync(al0, &sAl[(row0     ) * LDAB + k * 16], LDAB);
        wmma::load_matrix_sync(ah1, &sAh[(row0 + 16) * LDAB + k * 16], LDAB);
        wmma::load_matrix_sync(al1, &sAl[(row0 + 16) * LDAB + k * 16], LDAB);
        #pragma unroll
        for (int n = 0; n < 4; n++) {
            wmma::fragment<wmma::matrix_b, 16, 16, 16, __nv_bfloat16, wmma::row_major> bh, bl;
            wmma::load_matrix_sync(bh, &sWh[(k * 16) * LDAB + n * 16], LDAB);
            wmma::load_matrix_sync(bl, &sWl[(k * 16) * LDAB + n * 16], LDAB);
            wmma::mma_sync(acc[0][n], ah0, bh, acc[0][n]);
            wmma::mma_sync(acc[0][n], al0, bh, acc[0][n]);
            wmma::mma_sync(acc[0][n], ah0, bl, acc[0][n]);
            wmma::mma_sync(acc[1][n], ah1, bh, acc[1][n]);
            wmma::mma_sync(acc[1][n], al1, bh, acc[1][n]);
            wmma::mma_sync(acc[1][n], ah1, bl, acc[1][n]);
        }
    }

    __syncthreads();   // all smem reads (A/W) complete before staging overwrites A
    float* st = sSt + row0 * LDST;   // warp-private 32x68 staging
    #pragma unroll
    for (int mi = 0; mi < 2; mi++)
        #pragma unroll
        for (int n = 0; n < 4; n++)
            wmma::store_matrix_sync(st + mi * 16 * LDST + n * 16, acc[mi][n],
                                    LDST, wmma::mem_row_major);
    __syncwarp();

    for (int i = lane; i < 32 * 16; i += 32) {
        int rr = i >> 4, cgp = i & 15;
        int n = node0 + row0 + rr;
        if (n >= NN) continue;
        float4 v = *(float4*)&st[rr * LDST + cgp * 4];
        float4 b = ((const float4*)&g_BC[m * 64])[cgp];
        v.x += b.x; v.y += b.y; v.z += b.z; v.w += b.w;
        if (m == 0) {
            int dg = g_deg[n];
            float dis = dg > 0 ? rsqrtf((float)dg) : 0.f;
            v.x *= dis; v.y *= dis; v.z *= dis; v.w *= dis;
        }
        __half2 h0 = __floats2half2_rn(v.x, v.y);
        __half2 h1 = __floats2half2_rn(v.z, v.w);
        uint2 u = make_uint2(*(unsigned int*)&h0, *(unsigned int*)&h1);
        if (m == 0) ((uint2*)g_zh)[n * 16 + cgp] = u;
        else        ((uint2*)g_yh)[((m - 1) * NN + n) * 16 + cgp] = u;
    }
}

// ---- parallel scan: per-block sums, then merged (scan-of-sums + local scan) ----
__global__ void __launch_bounds__(256) k_bsum() {
    __shared__ int s[256];
    int t = threadIdx.x;
    int idx = blockIdx.x * 256 + t;
    int v = idx < NN ? g_cnt[idx] : 0;
    s[t] = v;
    __syncthreads();
    for (int d = 128; d > 0; d >>= 1) {
        if (t < d) s[t] += s[t + d];
        __syncthreads();
    }
    if (t == 0) g_bsum[blockIdx.x] = s[0];
}

__global__ void __launch_bounds__(256) k_off2() {
    __shared__ int sb[256];
    __shared__ int s[256];
    int t = threadIdx.x;
    int bv = t < NB ? g_bsum[t] : 0;
    sb[t] = bv;
    int idx = blockIdx.x * 256 + t;
    int v = idx < NN ? g_cnt[idx] : 0;
    s[t] = v;
    __syncthreads();
    #pragma unroll
    for (int d = 1; d < 256; d <<= 1) {
        int ub = (t >= d) ? sb[t - d] : 0;
        int u  = (t >= d) ? s[t - d] : 0;
        __syncthreads();
        sb[t] += ub;
        s[t]  += u;
        __syncthreads();
    }
    int boff = blockIdx.x > 0 ? sb[blockIdx.x - 1] : 0;
    int excl = s[t] - v + boff;
    if (idx < NN) { g_off[idx] = excl; g_cur[idx] = excl; }
    if (idx == NN - 1) g_off[NN] = NE;
}

__global__ void k_scatter(const int* __restrict__ ei, const int* __restrict__ et) {
    int e = blockIdx.x * blockDim.x + threadIdx.x;
    if (e >= NE) return;
    int r = ei[e], c = ei[NE + e], tp = et[e];
    int pos = atomicAdd(&g_cur[r], 1);
    g_es[pos] = c | (tp << 16);
}

// ================= sorted edge pass =================
// One warp per dst node; dual independent accumulator chains for MLP.
__global__ void __launch_bounds__(256) k_edge2() {
    int t = threadIdx.x;
    int node = blockIdx.x * 8 + (t >> 5);
    if (node >= NN) return;
    int l = t & 31;
    int beg = g_off[node], end = g_off[node + 1];

    float2 gcn0 = make_float2(0.f, 0.f), gcn1 = make_float2(0.f, 0.f);
    float2 ss0  = make_float2(0.f, 0.f), ss1  = make_float2(0.f, 0.f);
    float2 nm0  = make_float2(0.f, 0.f), nm1  = make_float2(0.f, 0.f);

    int i = beg;
    for (; i + 1 < end; i += 2) {
        int pka = __ldg(&g_es[i]);
        int pkb = __ldg(&g_es[i + 1]);
        int ca = pka & 0xFFFF, ta = pka >> 16;
        int cb = pkb & 0xFFFF, tb = pkb >> 16;
        unsigned int zua = __ldg(&g_zh[ca * 32 + l]);
        unsigned int yua = __ldg(&g_yh[(ta * NN + ca) * 32 + l]);
        unsigned int zub = __ldg(&g_zh[cb * 32 + l]);
        unsigned int yub = __ldg(&g_yh[(tb * NN + cb) * 32 + l]);
        float2 za = __half22float2(*(__half2*)&zua);
        float2 ya = __half22float2(*(__half2*)&yua);
        float2 zb = __half22float2(*(__half2*)&zub);
        float2 yb = __half22float2(*(__half2*)&yub);
        float exa = __expf(ya.x), eya = __expf(ya.y);
        float exb = __expf(yb.x), eyb = __expf(yb.y);
        gcn0.x += za.x;        gcn0.y += za.y;
        ss0.x  += exa;         ss0.y  += eya;
        nm0.x  += ya.x * exa;  nm0.y  += ya.y * eya;
        gcn1.x += zb.x;        gcn1.y += zb.y;
        ss1.x  += exb;         ss1.y  += eyb;
        nm1.x  += yb.x * exb;  nm1.y  += yb.y * eyb;
    }
    if (i < end) {
        int pk = __ldg(&g_es[i]);
        int c = pk & 0xFFFF, tp = pk >> 16;
        unsigned int zu = __ldg(&g_zh[c * 32 + l]);
        unsigned int yu = __ldg(&g_yh[(tp * NN + c) * 32 + l]);
        float2 zv = __half22float2(*(__half2*)&zu);
        float2 yv = __half22float2(*(__half2*)&yu);
        float ex = __expf(yv.x), ey = __expf(yv.y);
        gcn0.x += zv.x;       gcn0.y += zv.y;
        ss0.x  += ex;         ss0.y  += ey;
        nm0.x  += yv.x * ex;  nm0.y  += yv.y * ey;
    }

    float2 gcn = make_float2(gcn0.x + gcn1.x, gcn0.y + gcn1.y);
    float2 ss  = make_float2(ss0.x + ss1.x,  ss0.y + ss1.y);
    float2 nm  = make_float2(nm0.x + nm1.x,  nm0.y + nm1.y);

    int dg = g_deg[node];
    float dis = dg > 0 ? rsqrtf((float)dg) : 0.f;
    float2 m;
    m.x = dis * gcn.x + 0.5f * fmaxf(nm.x / (ss.x + 1e-16f), 0.f);
    m.y = dis * gcn.y + 0.5f * fmaxf(nm.y / (ss.y + 1e-16f), 0.f);
    ((float2*)g_m)[node * 32 + l] = m;
}

// ================= output GEMM =================
#define SA_STRIDE 68
__global__ void __launch_bounds__(256) k_out(const float* __restrict__ Wout,
                                             const float* __restrict__ bout,
                                             float* __restrict__ out) {
    __shared__ float sMT[H * SA_STRIDE];
    __shared__ float sWo[H * H];
    __shared__ float sB[H];
    int t = threadIdx.x;
    int node0 = blockIdx.x * 64;

    for (int i = t; i < 64 * 16; i += 256) {
        int nd = i >> 4, kg = i & 15;
        float4 mm = make_float4(0.f, 0.f, 0.f, 0.f);
        if (node0 + nd < NN) mm = ((const float4*)g_m)[(node0 + nd) * 16 + kg];
        sMT[(kg * 4 + 0) * SA_STRIDE + nd] = mm.x;
        sMT[(kg * 4 + 1) * SA_STRIDE + nd] = mm.y;
        sMT[(kg * 4 + 2) * SA_STRIDE + nd] = mm.z;
        sMT[(kg * 4 + 3) * SA_STRIDE + nd] = mm.w;
    }

    #pragma unroll
    for (int i = 0; i < 4; i++)
        ((float4*)sWo)[t + 256 * i] = ((const float4*)Wout)[t + 256 * i];
    if (t < H) sB[t] = bout[t];
    __syncthreads();

    int rg = t >> 4, cg = t & 15;
    float4 b = ((float4*)sB)[cg];
    float4 acc[4];
    #pragma unroll
    for (int j = 0; j < 4; j++) acc[j] = b;

    #pragma unroll 16
    for (int k = 0; k < H; k++) {
        float4 av = *(const float4*)&sMT[k * SA_STRIDE + rg * 4];
        float4 w  = ((const float4*)sWo)[k * 16 + cg];
        acc[0].x += av.x * w.x; acc[0].y += av.x * w.y; acc[0].z += av.x * w.z; acc[0].w += av.x * w.w;
        acc[1].x += av.y * w.x; acc[1].y += av.y * w.y; acc[1].z += av.y * w.z; acc[1].w += av.y * w.w;
        acc[2].x += av.z * w.x; acc[2].y += av.z * w.y; acc[2].z += av.z * w.z; acc[2].w += av.z * w.w;
        acc[3].x += av.w * w.x; acc[3].y += av.w * w.y; acc[3].z += av.w * w.z; acc[3].w += av.w * w.w;
    }

    int nbase = node0 + rg * 4;
    #pragma unroll
    for (int j = 0; j < 4; j++) {
        int n = nbase + j;
        if (n < NN) ((float4*)out)[n * 16 + cg] = acc[j];
    }
}

extern "C" void kernel_launch(void* const* d_in, const int* in_sizes, int n_in,
                              void* d_out, int out_size) {
    const float* risk = (const float*)d_in[0];
    // d_in[1] = edge_weight (unused by the reference)
    const float* Win  = (const float*)d_in[2];
    const float* bin  = (const float*)d_in[3];
    const float* Wrel = (const float*)d_in[4];
    const float* Wout = (const float*)d_in[5];
    const float* bout = (const float*)d_in[6];
    const int*   ei   = (const int*)d_in[7];   // [2, NE]: row (dst), col (src)
    const int*   et   = (const int*)d_in[8];
    float* out = (float*)d_out;

    cudaFuncSetAttribute(k_node_tc, cudaFuncAttributeMaxDynamicSharedMemorySize, TCN_SMEM);

    // NOTE: k_node_tc stays the 4th launch — the ncu capture profiles launch #4.
    k_prep<<<512, 256>>>(risk);
    k_wcomb<<<(6 * H * H + 255) / 256, 256>>>(Win, bin, Wrel);
    k_deg<<<(NE + 255) / 256, 256>>>(ei);
    k_node_tc<<<dim3((NN + 127) / 128, 6), 128, TCN_SMEM>>>();
    k_bsum<<<NB, 256>>>();
    k_off2<<<NB, 256>>>();
    k_scatter<<<(NE + 255) / 256, 256>>>(ei, et);
    k_edge2<<<(NN + 7) / 8, 256>>>();
    k_out<<<(NN + 63) / 64, 256>>>(Wout, bout, out);
}

// round 12
// speedup vs baseline: 1.1366x; 1.1366x over previous
#include <cuda_runtime.h>
#include <cuda_fp16.h>
#include <mma.h>
#include <cstdint>

using namespace nvcuda;

#define NN 50000
#define NE 800000
#define H  64
#define REL 5
#define NB 196          // (NN + 255) / 256

// ---- device scratch (static globals; no runtime allocation) ----
__device__ unsigned int g_zh[NN * 32];           // z as half2   (6.4 MB)
__device__ unsigned int g_yh[REL * NN * 32];     // y_r as half2 (32 MB)
__device__ float g_m[NN * H];            // fused message (edge-pass output)
__device__ int   g_deg[NN];              // col-degree (for gcn norm)
__device__ int   g_cnt[NN];              // row-degree (for sort)
__device__ int   g_off[NN + 1];          // CSR offsets by dst
__device__ int   g_cur[NN];              // scatter cursors
__device__ int   g_es[NE];               // sorted packed edges: src | type<<16
__device__ int   g_bsum[NB];             // per-block sums for scan
__device__ __half g_Ah[NN * H];          // risk hi split, fp16 (6.4 MB)
__device__ __half g_Al[NN * H];          // risk lo split, fp16
__device__ __half g_Wh[6 * H * H];       // combined weights, fp16 (single)
__device__ float g_BC[6 * H];            // [b | b@W_rel_r]

// ================= prep: zero counters + fp16-split A =================
__global__ void k_prep(const float* __restrict__ risk) {
    int i = blockIdx.x * blockDim.x + threadIdx.x;
    int stride = gridDim.x * blockDim.x;
    for (int j = i; j < NN; j += stride) { g_deg[j] = 0; g_cnt[j] = 0; }
    for (int j = i; j < NN * 16; j += stride) {
        float4 v = ((const float4*)risk)[j];
        __half hx = __float2half_rn(v.x), hy = __float2half_rn(v.y);
        __half hz = __float2half_rn(v.z), hw = __float2half_rn(v.w);
        ((__half2*)g_Ah)[j * 2]     = __half2(hx, hy);
        ((__half2*)g_Ah)[j * 2 + 1] = __half2(hz, hw);
        ((__half2*)g_Al)[j * 2]     = __half2(
            __float2half_rn(v.x - __half2float(hx)),
            __float2half_rn(v.y - __half2float(hy)));
        ((__half2*)g_Al)[j * 2 + 1] = __half2(
            __float2half_rn(v.z - __half2float(hz)),
            __float2half_rn(v.w - __half2float(hw)));
    }
}

// Combined weights (fp16): W[0]=W_in, W[1+r]=W_in@W_rel[r]; BC in fp32.
__global__ void k_wcomb(const float* __restrict__ Win, const float* __restrict__ bin,
                        const float* __restrict__ Wrel) {
    int idx = blockIdx.x * blockDim.x + threadIdx.x;
    if (idx >= 6 * H * H) return;
    int m = idx >> 12, k = (idx >> 6) & 63, h = idx & 63;
    float s;
    if (m == 0) {
        s = Win[k * H + h];
        if (k == 0) g_BC[h] = bin[h];
    } else {
        const float* Wr = Wrel + (m - 1) * H * H;
        s = 0.f;
        #pragma unroll 8
        for (int j = 0; j < H; j++) s += Win[k * H + j] * Wr[j * H + h];
        if (k == 0) {
            float sb = 0.f;
            for (int j = 0; j < H; j++) sb += bin[j] * Wr[j * H + h];
            g_BC[m * H + h] = sb;
        }
    }
    g_Wh[idx] = __float2half_rn(s);
}

__global__ void k_deg(const int* __restrict__ ei) {
    int e = blockIdx.x * blockDim.x + threadIdx.x;
    if (e < NE) {
        atomicAdd(&g_deg[ei[NE + e]], 1);   // col-degree (norm)
        atomicAdd(&g_cnt[ei[e]], 1);        // row-degree (sort)
    }
}

// ================= tensor-core node GEMM (wmma fp16 split-2) =================
// Grid (391, 6): block = (node-tile of 128, matrix m). 8 warps; warp w owns 16 rows.
// D = Ah@B + Al@B (fp16 A hi/lo, single fp16 B), fp32 accumulate.
#define LDAB 72      // fp16 leading dim (mult of 8 elems = 16B)
#define LDST 68      // float leading dim for staging
#define TCN_SMEM (2 * 128 * LDAB * 2 + 64 * LDAB * 2)   // 46080 B

__global__ void __launch_bounds__(256) k_node_tc() {
    extern __shared__ char smc[];
    __half* sAh = (__half*)smc;
    __half* sAl = sAh + 128 * LDAB;
    __half* sWh = sAl + 128 * LDAB;
    float*  sSt = (float*)smc;      // staging reuses A region (34.8KB < 36.9KB)

    int t = threadIdx.x;
    int w = t >> 5, lane = t & 31;
    int node0 = blockIdx.x * 128;
    int m = blockIdx.y;

    // fill A tile (half2 copies; guard tail tile)
    for (int i = t; i < 128 * 32; i += 256) {
        int r = i >> 5, c2 = i & 31;
        int n = node0 + r;
        __half2 vh = __half2(__float2half_rn(0.f), __float2half_rn(0.f));
        __half2 vl = vh;
        if (n < NN) {
            vh = ((const __half2*)g_Ah)[n * 32 + c2];
            vl = ((const __half2*)g_Al)[n * 32 + c2];
        }
        ((__half2*)(sAh + r * LDAB))[c2] = vh;
        ((__half2*)(sAl + r * LDAB))[c2] = vl;
    }
    // fill W tile
    for (int i = t; i < 64 * 32; i += 256) {
        int r = i >> 5, c2 = i & 31;
        ((__half2*)(sWh + r * LDAB))[c2] = ((const __half2*)g_Wh)[m * 2048 + i];
    }
    __syncthreads();

    wmma::fragment<wmma::accumulator, 16, 16, 16, float> acc[4];
    #pragma unroll
    for (int n = 0; n < 4; n++) wmma::fill_fragment(acc[n], 0.f);

    #pragma unroll
    for (int k = 0; k < 4; k++) {
        wmma::fragment<wmma::matrix_a, 16, 16, 16, __half, wmma::row_major> ah, al;
        wmma::load_matrix_sync(ah, &sAh[(w * 16) * LDAB + k * 16], LDAB);
        wmma::load_matrix_sync(al, &sAl[(w * 16) * LDAB + k * 16], LDAB);
        #pragma unroll
        for (int n = 0; n < 4; n++) {
            wmma::fragment<wmma::matrix_b, 16, 16, 16, __half, wmma::row_major> bh;
            wmma::load_matrix_sync(bh, &sWh[(k * 16) * LDAB + n * 16], LDAB);
            wmma::mma_sync(acc[n], ah, bh, acc[n]);
            wmma::mma_sync(acc[n], al, bh, acc[n]);
        }
    }

    __syncthreads();   // all smem reads (A/W) complete before staging overwrites A
    float* st = sSt + (w * 16) * LDST;   // warp-private 16x68 staging
    #pragma unroll
    for (int n = 0; n < 4; n++)
        wmma::store_matrix_sync(st + n * 16, acc[n], LDST, wmma::mem_row_major);
    __syncwarp();

    for (int i = lane; i < 16 * 16; i += 32) {
        int rr = i >> 4, cgp = i & 15;
        int n = node0 + w * 16 + rr;
        if (n >= NN) continue;
        float4 v = *(float4*)&st[rr * LDST + cgp * 4];
        float4 b = ((const float4*)&g_BC[m * 64])[cgp];
        v.x += b.x; v.y += b.y; v.z += b.z; v.w += b.w;
        if (m == 0) {
            int dg = g_deg[n];
            float dis = dg > 0 ? rsqrtf((float)dg) : 0.f;
            v.x *= dis; v.y *= dis; v.z *= dis; v.w *= dis;
        }
        __half2 h0 = __floats2half2_rn(v.x, v.y);
        __half2 h1 = __floats2half2_rn(v.z, v.w);
        uint2 u = make_uint2(*(unsigned int*)&h0, *(unsigned int*)&h1);
        if (m == 0) ((uint2*)g_zh)[n * 16 + cgp] = u;
        else        ((uint2*)g_yh)[((m - 1) * NN + n) * 16 + cgp] = u;
    }
}

// ---- parallel scan: per-block sums, then merged (scan-of-sums + local scan) ----
__global__ void __launch_bounds__(256) k_bsum() {
    __shared__ int s[256];
    int t = threadIdx.x;
    int idx = blockIdx.x * 256 + t;
    int v = idx < NN ? g_cnt[idx] : 0;
    s[t] = v;
    __syncthreads();
    for (int d = 128; d > 0; d >>= 1) {
        if (t < d) s[t] += s[t + d];
        __syncthreads();
    }
    if (t == 0) g_bsum[blockIdx.x] = s[0];
}

__global__ void __launch_bounds__(256) k_off2() {
    __shared__ int sb[256];
    __shared__ int s[256];
    int t = threadIdx.x;
    int bv = t < NB ? g_bsum[t] : 0;
    sb[t] = bv;
    int idx = blockIdx.x * 256 + t;
    int v = idx < NN ? g_cnt[idx] : 0;
    s[t] = v;
    __syncthreads();
    #pragma unroll
    for (int d = 1; d < 256; d <<= 1) {
        int ub = (t >= d) ? sb[t - d] : 0;
        int u  = (t >= d) ? s[t - d] : 0;
        __syncthreads();
        sb[t] += ub;
        s[t]  += u;
        __syncthreads();
    }
    int boff = blockIdx.x > 0 ? sb[blockIdx.x - 1] : 0;
    int excl = s[t] - v + boff;
    if (idx < NN) { g_off[idx] = excl; g_cur[idx] = excl; }
    if (idx == NN - 1) g_off[NN] = NE;
}

__global__ void k_scatter(const int* __restrict__ ei, const int* __restrict__ et) {
    int e = blockIdx.x * blockDim.x + threadIdx.x;
    if (e >= NE) return;
    int r = ei[e], c = ei[NE + e], tp = et[e];
    int pos = atomicAdd(&g_cur[r], 1);
    g_es[pos] = c | (tp << 16);
}

// ================= sorted edge pass =================
// One warp per dst node; dual independent accumulator chains for MLP.
__global__ void __launch_bounds__(256) k_edge2() {
    int t = threadIdx.x;
    int node = blockIdx.x * 8 + (t >> 5);
    if (node >= NN) return;
    int l = t & 31;
    int beg = g_off[node], end = g_off[node + 1];

    float2 gcn0 = make_float2(0.f, 0.f), gcn1 = make_float2(0.f, 0.f);
    float2 ss0  = make_float2(0.f, 0.f), ss1  = make_float2(0.f, 0.f);
    float2 nm0  = make_float2(0.f, 0.f), nm1  = make_float2(0.f, 0.f);

    int i = beg;
    for (; i + 1 < end; i += 2) {
        int pka = __ldg(&g_es[i]);
        int pkb = __ldg(&g_es[i + 1]);
        int ca = pka & 0xFFFF, ta = pka >> 16;
        int cb = pkb & 0xFFFF, tb = pkb >> 16;
        unsigned int zua = __ldg(&g_zh[ca * 32 + l]);
        unsigned int yua = __ldg(&g_yh[(ta * NN + ca) * 32 + l]);
        unsigned int zub = __ldg(&g_zh[cb * 32 + l]);
        unsigned int yub = __ldg(&g_yh[(tb * NN + cb) * 32 + l]);
        float2 za = __half22float2(*(__half2*)&zua);
        float2 ya = __half22float2(*(__half2*)&yua);
        float2 zb = __half22float2(*(__half2*)&zub);
        float2 yb = __half22float2(*(__half2*)&yub);
        float exa = __expf(ya.x), eya = __expf(ya.y);
        float exb = __expf(yb.x), eyb = __expf(yb.y);
        gcn0.x += za.x;        gcn0.y += za.y;
        ss0.x  += exa;         ss0.y  += eya;
        nm0.x  += ya.x * exa;  nm0.y  += ya.y * eya;
        gcn1.x += zb.x;        gcn1.y += zb.y;
        ss1.x  += exb;         ss1.y  += eyb;
        nm1.x  += yb.x * exb;  nm1.y  += yb.y * eyb;
    }
    if (i < end) {
        int pk = __ldg(&g_es[i]);
        int c = pk & 0xFFFF, tp = pk >> 16;
        unsigned int zu = __ldg(&g_zh[c * 32 + l]);
        unsigned int yu = __ldg(&g_yh[(tp * NN + c) * 32 + l]);
        float2 zv = __half22float2(*(__half2*)&zu);
        float2 yv = __half22float2(*(__half2*)&yu);
        float ex = __expf(yv.x), ey = __expf(yv.y);
        gcn0.x += zv.x;       gcn0.y += zv.y;
        ss0.x  += ex;         ss0.y  += ey;
        nm0.x  += yv.x * ex;  nm0.y  += yv.y * ey;
    }

    float2 gcn = make_float2(gcn0.x + gcn1.x, gcn0.y + gcn1.y);
    float2 ss  = make_float2(ss0.x + ss1.x,  ss0.y + ss1.y);
    float2 nm  = make_float2(nm0.x + nm1.x,  nm0.y + nm1.y);

    int dg = g_deg[node];
    float dis = dg > 0 ? rsqrtf((float)dg) : 0.f;
    float2 m;
    m.x = dis * gcn.x + 0.5f * fmaxf(nm.x / (ss.x + 1e-16f), 0.f);
    m.y = dis * gcn.y + 0.5f * fmaxf(nm.y / (ss.y + 1e-16f), 0.f);
    ((float2*)g_m)[node * 32 + l] = m;
}

// ================= output GEMM =================
#define SA_STRIDE 68
__global__ void __launch_bounds__(256) k_out(const float* __restrict__ Wout,
                                             const float* __restrict__ bout,
                                             float* __restrict__ out) {
    __shared__ float sMT[H * SA_STRIDE];
    __shared__ float sWo[H * H];
    __shared__ float sB[H];
    int t = threadIdx.x;
    int node0 = blockIdx.x * 64;

    for (int i = t; i < 64 * 16; i += 256) {
        int nd = i >> 4, kg = i & 15;
        float4 mm = make_float4(0.f, 0.f, 0.f, 0.f);
        if (node0 + nd < NN) mm = ((const float4*)g_m)[(node0 + nd) * 16 + kg];
        sMT[(kg * 4 + 0) * SA_STRIDE + nd] = mm.x;
        sMT[(kg * 4 + 1) * SA_STRIDE + nd] = mm.y;
        sMT[(kg * 4 + 2) * SA_STRIDE + nd] = mm.z;
        sMT[(kg * 4 + 3) * SA_STRIDE + nd] = mm.w;
    }

    #pragma unroll
    for (int i = 0; i < 4; i++)
        ((float4*)sWo)[t + 256 * i] = ((const float4*)Wout)[t + 256 * i];
    if (t < H) sB[t] = bout[t];
    __syncthreads();

    int rg = t >> 4, cg = t & 15;
    float4 b = ((float4*)sB)[cg];
    float4 acc[4];
    #pragma unroll
    for (int j = 0; j < 4; j++) acc[j] = b;

    #pragma unroll 16
    for (int k = 0; k < H; k++) {
        float4 av = *(const float4*)&sMT[k * SA_STRIDE + rg * 4];
        float4 w  = ((const float4*)sWo)[k * 16 + cg];
        acc[0].x += av.x * w.x; acc[0].y += av.x * w.y; acc[0].z += av.x * w.z; acc[0].w += av.x * w.w;
        acc[1].x += av.y * w.x; acc[1].y += av.y * w.y; acc[1].z += av.y * w.z; acc[1].w += av.y * w.w;
        acc[2].x += av.z * w.x; acc[2].y += av.z * w.y; acc[2].z += av.z * w.z; acc[2].w += av.z * w.w;
        acc[3].x += av.w * w.x; acc[3].y += av.w * w.y; acc[3].z += av.w * w.z; acc[3].w += av.w * w.w;
    }

    int nbase = node0 + rg * 4;
    #pragma unroll
    for (int j = 0; j < 4; j++) {
        int n = nbase + j;
        if (n < NN) ((float4*)out)[n * 16 + cg] = acc[j];
    }
}

extern "C" void kernel_launch(void* const* d_in, const int* in_sizes, int n_in,
                              void* d_out, int out_size) {
    const float* risk = (const float*)d_in[0];
    // d_in[1] = edge_weight (unused by the reference)
    const float* Win  = (const float*)d_in[2];
    const float* bin  = (const float*)d_in[3];
    const float* Wrel = (const float*)d_in[4];
    const float* Wout = (const float*)d_in[5];
    const float* bout = (const float*)d_in[6];
    const int*   ei   = (const int*)d_in[7];   // [2, NE]: row (dst), col (src)
    const int*   et   = (const int*)d_in[8];
    float* out = (float*)d_out;

    cudaFuncSetAttribute(k_node_tc, cudaFuncAttributeMaxDynamicSharedMemorySize, TCN_SMEM);

    // NOTE: k_node_tc stays the 4th launch — the ncu capture profiles launch #4.
    k_prep<<<512, 256>>>(risk);
    k_wcomb<<<(6 * H * H + 255) / 256, 256>>>(Win, bin, Wrel);
    k_deg<<<(NE + 255) / 256, 256>>>(ei);
    k_node_tc<<<dim3((NN + 127) / 128, 6), 256, TCN_SMEM>>>();
    k_bsum<<<NB, 256>>>();
    k_off2<<<NB, 256>>>();
    k_scatter<<<(NE + 255) / 256, 256>>>(ei, et);
    k_edge2<<<(NN + 7) / 8, 256>>>();
    k_out<<<(NN + 63) / 64, 256>>>(Wout, bout, out);
}

// round 13
// speedup vs baseline: 1.3420x; 1.1807x over previous
#include <cuda_runtime.h>
#include <cuda_fp16.h>
#include <mma.h>
#include <cstdint>

using namespace nvcuda;

#define NN 50000
#define NE 800000
#define H  64
#define REL 5
#define NB 196          // (NN + 255) / 256

// ---- device scratch (static globals; no runtime allocation) ----
__device__ unsigned int g_zh[NN * 32];           // z as half2   (6.4 MB)
__device__ unsigned int g_yh[REL * NN * 32];     // y_r as half2 (32 MB)
__device__ unsigned int g_mh[NN * 32];           // m hi as half2
__device__ unsigned int g_ml[NN * 32];           // m lo as half2
__device__ int   g_deg[NN];              // col-degree (for gcn norm)
__device__ int   g_cnt[NN];              // row-degree (for sort)
__device__ int   g_off[NN + 1];          // CSR offsets by dst
__device__ int   g_cur[NN];              // scatter cursors
__device__ int   g_es[NE];               // sorted packed edges: src | type<<16
__device__ int   g_bsum[NB];             // per-block sums for scan
__device__ __half g_Ah[NN * H];          // risk hi split, fp16 (6.4 MB)
__device__ __half g_Al[NN * H];          // risk lo split, fp16
__device__ __half g_Wh[6 * H * H];       // combined weights, fp16 (single)
__device__ __half g_Woh[H * H];          // W_out hi split
__device__ __half g_Wol[H * H];          // W_out lo split
__device__ float g_BC[6 * H];            // [b | b@W_rel_r]

__device__ __forceinline__ void cp16(void* s, const void* g) {
    uint32_t sa = (uint32_t)__cvta_generic_to_shared(s);
    asm volatile("cp.async.ca.shared.global [%0], [%1], 16;" :: "r"(sa), "l"(g));
}
__device__ __forceinline__ void cp_commit_wait() {
    asm volatile("cp.async.commit_group;");
    asm volatile("cp.async.wait_group 0;" ::: "memory");
}

// ================= prep: zero counters + fp16 splits (A, Wout) ============
__global__ void k_prep(const float* __restrict__ risk, const float* __restrict__ Wout) {
    int i = blockIdx.x * blockDim.x + threadIdx.x;
    int stride = gridDim.x * blockDim.x;
    for (int j = i; j < NN; j += stride) { g_deg[j] = 0; g_cnt[j] = 0; }
    for (int j = i; j < NN * 16; j += stride) {
        float4 v = ((const float4*)risk)[j];
        __half hx = __float2half_rn(v.x), hy = __float2half_rn(v.y);
        __half hz = __float2half_rn(v.z), hw = __float2half_rn(v.w);
        ((__half2*)g_Ah)[j * 2]     = __half2(hx, hy);
        ((__half2*)g_Ah)[j * 2 + 1] = __half2(hz, hw);
        ((__half2*)g_Al)[j * 2]     = __half2(
            __float2half_rn(v.x - __half2float(hx)),
            __float2half_rn(v.y - __half2float(hy)));
        ((__half2*)g_Al)[j * 2 + 1] = __half2(
            __float2half_rn(v.z - __half2float(hz)),
            __float2half_rn(v.w - __half2float(hw)));
    }
    for (int j = i; j < H * H; j += stride) {
        float v = Wout[j];
        __half hi = __float2half_rn(v);
        g_Woh[j] = hi;
        g_Wol[j] = __float2half_rn(v - __half2float(hi));
    }
}

// Combined weights (fp16): W[0]=W_in, W[1+r]=W_in@W_rel[r]; BC in fp32.
__global__ void k_wcomb(const float* __restrict__ Win, const float* __restrict__ bin,
                        const float* __restrict__ Wrel) {
    int idx = blockIdx.x * blockDim.x + threadIdx.x;
    if (idx >= 6 * H * H) return;
    int m = idx >> 12, k = (idx >> 6) & 63, h = idx & 63;
    float s;
    if (m == 0) {
        s = Win[k * H + h];
        if (k == 0) g_BC[h] = bin[h];
    } else {
        const float* Wr = Wrel + (m - 1) * H * H;
        s = 0.f;
        #pragma unroll 8
        for (int j = 0; j < H; j++) s += Win[k * H + j] * Wr[j * H + h];
        if (k == 0) {
            float sb = 0.f;
            for (int j = 0; j < H; j++) sb += bin[j] * Wr[j * H + h];
            g_BC[m * H + h] = sb;
        }
    }
    g_Wh[idx] = __float2half_rn(s);
}

__global__ void k_deg(const int* __restrict__ ei) {
    int e = blockIdx.x * blockDim.x + threadIdx.x;
    if (e < NE) {
        atomicAdd(&g_deg[ei[NE + e]], 1);   // col-degree (norm)
        atomicAdd(&g_cnt[ei[e]], 1);        // row-degree (sort)
    }
}

// ================= tensor-core node GEMM (wmma fp16 split-2) =================
// Grid (391, 6): block = (node-tile of 128, matrix m). 8 warps; warp w owns 16 rows.
// D = Ah@B + Al@B, fp32 accumulate. Fills via cp.async.
#define LDAB 72      // fp16 leading dim (mult of 8 elems = 16B)
#define LDST 68      // float leading dim for staging
#define TCN_SMEM (2 * 128 * LDAB * 2 + 64 * LDAB * 2)   // 46080 B

__global__ void __launch_bounds__(256) k_node_tc() {
    extern __shared__ char smc[];
    __half* sAh = (__half*)smc;
    __half* sAl = sAh + 128 * LDAB;
    __half* sWh = sAl + 128 * LDAB;
    float*  sSt = (float*)smc;      // staging reuses A region (34.8KB < 36.9KB)

    int t = threadIdx.x;
    int w = t >> 5, lane = t & 31;
    int node0 = blockIdx.x * 128;
    int m = blockIdx.y;

    // A fill via cp.async: 2048 16B chunks (Ah, Al)
    for (int i = t; i < 2048; i += 256) {
        int arr = i >> 10;
        int rc = i & 1023;
        int r = rc >> 3, c8 = rc & 7;
        __half* sdst = (arr ? sAl : sAh) + r * LDAB + c8 * 8;
        if (node0 + r < NN) {
            const __half* gsrc = (arr ? g_Al : g_Ah) + (node0 + r) * 64 + c8 * 8;
            cp16(sdst, gsrc);
        } else {
            *(uint4*)sdst = make_uint4(0, 0, 0, 0);
        }
    }
    // W fill: 512 chunks
    for (int i = t; i < 512; i += 256) {
        int r = i >> 3, c8 = i & 7;
        cp16(sWh + r * LDAB + c8 * 8, g_Wh + m * 4096 + r * 64 + c8 * 8);
    }
    cp_commit_wait();
    __syncthreads();

    wmma::fragment<wmma::accumulator, 16, 16, 16, float> acc[4];
    #pragma unroll
    for (int n = 0; n < 4; n++) wmma::fill_fragment(acc[n], 0.f);

    #pragma unroll
    for (int k = 0; k < 4; k++) {
        wmma::fragment<wmma::matrix_a, 16, 16, 16, __half, wmma::row_major> ah, al;
        wmma::load_matrix_sync(ah, &sAh[(w * 16) * LDAB + k * 16], LDAB);
        wmma::load_matrix_sync(al, &sAl[(w * 16) * LDAB + k * 16], LDAB);
        #pragma unroll
        for (int n = 0; n < 4; n++) {
            wmma::fragment<wmma::matrix_b, 16, 16, 16, __half, wmma::row_major> bh;
            wmma::load_matrix_sync(bh, &sWh[(k * 16) * LDAB + n * 16], LDAB);
            wmma::mma_sync(acc[n], ah, bh, acc[n]);
            wmma::mma_sync(acc[n], al, bh, acc[n]);
        }
    }

    __syncthreads();   // all smem reads (A/W) complete before staging overwrites A
    float* st = sSt + (w * 16) * LDST;   // warp-private 16x68 staging
    #pragma unroll
    for (int n = 0; n < 4; n++)
        wmma::store_matrix_sync(st + n * 16, acc[n], LDST, wmma::mem_row_major);
    __syncwarp();

    for (int i = lane; i < 16 * 16; i += 32) {
        int rr = i >> 4, cgp = i & 15;
        int n = node0 + w * 16 + rr;
        if (n >= NN) continue;
        float4 v = *(float4*)&st[rr * LDST + cgp * 4];
        float4 b = ((const float4*)&g_BC[m * 64])[cgp];
        v.x += b.x; v.y += b.y; v.z += b.z; v.w += b.w;
        if (m == 0) {
            int dg = g_deg[n];
            float dis = dg > 0 ? rsqrtf((float)dg) : 0.f;
            v.x *= dis; v.y *= dis; v.z *= dis; v.w *= dis;
        }
        __half2 h0 = __floats2half2_rn(v.x, v.y);
        __half2 h1 = __floats2half2_rn(v.z, v.w);
        uint2 u = make_uint2(*(unsigned int*)&h0, *(unsigned int*)&h1);
        if (m == 0) ((uint2*)g_zh)[n * 16 + cgp] = u;
        else        ((uint2*)g_yh)[((m - 1) * NN + n) * 16 + cgp] = u;
    }
}

// ---- parallel scan: per-block sums, then merged (scan-of-sums + local scan) ----
__global__ void __launch_bounds__(256) k_bsum() {
    __shared__ int s[256];
    int t = threadIdx.x;
    int idx = blockIdx.x * 256 + t;
    int v = idx < NN ? g_cnt[idx] : 0;
    s[t] = v;
    __syncthreads();
    for (int d = 128; d > 0; d >>= 1) {
        if (t < d) s[t] += s[t + d];
        __syncthreads();
    }
    if (t == 0) g_bsum[blockIdx.x] = s[0];
}

__global__ void __launch_bounds__(256) k_off2() {
    __shared__ int sb[256];
    __shared__ int s[256];
    int t = threadIdx.x;
    int bv = t < NB ? g_bsum[t] : 0;
    sb[t] = bv;
    int idx = blockIdx.x * 256 + t;
    int v = idx < NN ? g_cnt[idx] : 0;
    s[t] = v;
    __syncthreads();
    #pragma unroll
    for (int d = 1; d < 256; d <<= 1) {
        int ub = (t >= d) ? sb[t - d] : 0;
        int u  = (t >= d) ? s[t - d] : 0;
        __syncthreads();
        sb[t] += ub;
        s[t]  += u;
        __syncthreads();
    }
    int boff = blockIdx.x > 0 ? sb[blockIdx.x - 1] : 0;
    int excl = s[t] - v + boff;
    if (idx < NN) { g_off[idx] = excl; g_cur[idx] = excl; }
    if (idx == NN - 1) g_off[NN] = NE;
}

__global__ void k_scatter(const int* __restrict__ ei, const int* __restrict__ et) {
    int e = blockIdx.x * blockDim.x + threadIdx.x;
    if (e >= NE) return;
    int r = ei[e], c = ei[NE + e], tp = et[e];
    int pos = atomicAdd(&g_cur[r], 1);
    g_es[pos] = c | (tp << 16);
}

// ================= sorted edge pass =================
// One warp per dst node; dual independent accumulator chains for MLP.
// Emits m as fp16 hi/lo for the wmma output GEMM.
__global__ void __launch_bounds__(256) k_edge2() {
    int t = threadIdx.x;
    int node = blockIdx.x * 8 + (t >> 5);
    if (node >= NN) return;
    int l = t & 31;
    int beg = g_off[node], end = g_off[node + 1];

    float2 gcn0 = make_float2(0.f, 0.f), gcn1 = make_float2(0.f, 0.f);
    float2 ss0  = make_float2(0.f, 0.f), ss1  = make_float2(0.f, 0.f);
    float2 nm0  = make_float2(0.f, 0.f), nm1  = make_float2(0.f, 0.f);

    int i = beg;
    for (; i + 1 < end; i += 2) {
        int pka = __ldg(&g_es[i]);
        int pkb = __ldg(&g_es[i + 1]);
        int ca = pka & 0xFFFF, ta = pka >> 16;
        int cb = pkb & 0xFFFF, tb = pkb >> 16;
        unsigned int zua = __ldg(&g_zh[ca * 32 + l]);
        unsigned int yua = __ldg(&g_yh[(ta * NN + ca) * 32 + l]);
        unsigned int zub = __ldg(&g_zh[cb * 32 + l]);
        unsigned int yub = __ldg(&g_yh[(tb * NN + cb) * 32 + l]);
        float2 za = __half22float2(*(__half2*)&zua);
        float2 ya = __half22float2(*(__half2*)&yua);
        float2 zb = __half22float2(*(__half2*)&zub);
        float2 yb = __half22float2(*(__half2*)&yub);
        float exa = __expf(ya.x), eya = __expf(ya.y);
        float exb = __expf(yb.x), eyb = __expf(yb.y);
        gcn0.x += za.x;        gcn0.y += za.y;
        ss0.x  += exa;         ss0.y  += eya;
        nm0.x  += ya.x * exa;  nm0.y  += ya.y * eya;
        gcn1.x += zb.x;        gcn1.y += zb.y;
        ss1.x  += exb;         ss1.y  += eyb;
        nm1.x  += yb.x * exb;  nm1.y  += yb.y * eyb;
    }
    if (i < end) {
        int pk = __ldg(&g_es[i]);
        int c = pk & 0xFFFF, tp = pk >> 16;
        unsigned int zu = __ldg(&g_zh[c * 32 + l]);
        unsigned int yu = __ldg(&g_yh[(tp * NN + c) * 32 + l]);
        float2 zv = __half22float2(*(__half2*)&zu);
        float2 yv = __half22float2(*(__half2*)&yu);
        float ex = __expf(yv.x), ey = __expf(yv.y);
        gcn0.x += zv.x;       gcn0.y += zv.y;
        ss0.x  += ex;         ss0.y  += ey;
        nm0.x  += yv.x * ex;  nm0.y  += yv.y * ey;
    }

    float2 gcn = make_float2(gcn0.x + gcn1.x, gcn0.y + gcn1.y);
    float2 ss  = make_float2(ss0.x + ss1.x,  ss0.y + ss1.y);
    float2 nm  = make_float2(nm0.x + nm1.x,  nm0.y + nm1.y);

    int dg = g_deg[node];
    float dis = dg > 0 ? rsqrtf((float)dg) : 0.f;
    float2 m;
    m.x = dis * gcn.x + 0.5f * fmaxf(nm.x / (ss.x + 1e-16f), 0.f);
    m.y = dis * gcn.y + 0.5f * fmaxf(nm.y / (ss.y + 1e-16f), 0.f);

    __half2 mh = __floats2half2_rn(m.x, m.y);
    float2 mhf = __half22float2(mh);
    __half2 ml = __floats2half2_rn(m.x - mhf.x, m.y - mhf.y);
    g_mh[node * 32 + l] = *(unsigned int*)&mh;
    g_ml[node * 32 + l] = *(unsigned int*)&ml;
}

// ================= output GEMM (wmma, 3-term split) =================
// Grid 391: 128 nodes/block, 8 warps. D = Mh@Woh + Ml@Woh + Mh@Wol.
#define KOUT_SMEM (2 * 128 * LDAB * 2 + 2 * 64 * LDAB * 2)   // 55296 B

__global__ void __launch_bounds__(256) k_out_tc(const float* __restrict__ bout,
                                                float* __restrict__ out) {
    extern __shared__ char smc[];
    __half* sMh = (__half*)smc;
    __half* sMl = sMh + 128 * LDAB;
    __half* sWh = sMl + 128 * LDAB;
    __half* sWl = sWh + 64 * LDAB;
    float*  sSt = (float*)smc;

    int t = threadIdx.x;
    int w = t >> 5, lane = t & 31;
    int node0 = blockIdx.x * 128;

    for (int i = t; i < 2048; i += 256) {
        int arr = i >> 10;
        int rc = i & 1023;
        int r = rc >> 3, c8 = rc & 7;
        __half* sdst = (arr ? sMl : sMh) + r * LDAB + c8 * 8;
        if (node0 + r < NN) {
            const __half* gsrc = (const __half*)(arr ? g_ml : g_mh) + (node0 + r) * 64 + c8 * 8;
            cp16(sdst, gsrc);
        } else {
            *(uint4*)sdst = make_uint4(0, 0, 0, 0);
        }
    }
    for (int i = t; i < 1024; i += 256) {
        int arr = i >> 9;
        int rc = i & 511;
        int r = rc >> 3, c8 = rc & 7;
        __half* sdst = (arr ? sWl : sWh) + r * LDAB + c8 * 8;
        const __half* gsrc = (arr ? g_Wol : g_Woh) + r * 64 + c8 * 8;
        cp16(sdst, gsrc);
    }
    cp_commit_wait();
    __syncthreads();

    wmma::fragment<wmma::accumulator, 16, 16, 16, float> acc[4];
    #pragma unroll
    for (int n = 0; n < 4; n++) wmma::fill_fragment(acc[n], 0.f);

    #pragma unroll
    for (int k = 0; k < 4; k++) {
        wmma::fragment<wmma::matrix_a, 16, 16, 16, __half, wmma::row_major> ah, al;
        wmma::load_matrix_sync(ah, &sMh[(w * 16) * LDAB + k * 16], LDAB);
        wmma::load_matrix_sync(al, &sMl[(w * 16) * LDAB + k * 16], LDAB);
        #pragma unroll
        for (int n = 0; n < 4; n++) {
            wmma::fragment<wmma::matrix_b, 16, 16, 16, __half, wmma::row_major> bh, bl;
            wmma::load_matrix_sync(bh, &sWh[(k * 16) * LDAB + n * 16], LDAB);
            wmma::load_matrix_sync(bl, &sWl[(k * 16) * LDAB + n * 16], LDAB);
            wmma::mma_sync(acc[n], ah, bh, acc[n]);
            wmma::mma_sync(acc[n], al, bh, acc[n]);
            wmma::mma_sync(acc[n], ah, bl, acc[n]);
        }
    }

    __syncthreads();
    float* st = sSt + (w * 16) * LDST;
    #pragma unroll
    for (int n = 0; n < 4; n++)
        wmma::store_matrix_sync(st + n * 16, acc[n], LDST, wmma::mem_row_major);
    __syncwarp();

    for (int i = lane; i < 16 * 16; i += 32) {
        int rr = i >> 4, cgp = i & 15;
        int n = node0 + w * 16 + rr;
        if (n >= NN) continue;
        float4 v = *(float4*)&st[rr * LDST + cgp * 4];
        float4 b = __ldg(&((const float4*)bout)[cgp]);
        v.x += b.x; v.y += b.y; v.z += b.z; v.w += b.w;
        ((float4*)out)[n * 16 + cgp] = v;
    }
}

extern "C" void kernel_launch(void* const* d_in, const int* in_sizes, int n_in,
                              void* d_out, int out_size) {
    const float* risk = (const float*)d_in[0];
    // d_in[1] = edge_weight (unused by the reference)
    const float* Win  = (const float*)d_in[2];
    const float* bin  = (const float*)d_in[3];
    const float* Wrel = (const float*)d_in[4];
    const float* Wout = (const float*)d_in[5];
    const float* bout = (const float*)d_in[6];
    const int*   ei   = (const int*)d_in[7];   // [2, NE]: row (dst), col (src)
    const int*   et   = (const int*)d_in[8];
    float* out = (float*)d_out;

    cudaFuncSetAttribute(k_node_tc, cudaFuncAttributeMaxDynamicSharedMemorySize, TCN_SMEM);
    cudaFuncSetAttribute(k_out_tc,  cudaFuncAttributeMaxDynamicSharedMemorySize, KOUT_SMEM);

    // NOTE: k_node_tc stays the 4th launch — the ncu capture profiles launch #4.
    k_prep<<<512, 256>>>(risk, Wout);
    k_wcomb<<<(6 * H * H + 255) / 256, 256>>>(Win, bin, Wrel);
    k_deg<<<(NE + 255) / 256, 256>>>(ei);
    k_node_tc<<<dim3((NN + 127) / 128, 6), 256, TCN_SMEM>>>();
    k_bsum<<<NB, 256>>>();
    k_off2<<<NB, 256>>>();
    k_scatter<<<(NE + 255) / 256, 256>>>(ei, et);
    k_edge2<<<(NN + 7) / 8, 256>>>();
    k_out_tc<<<(NN + 127) / 128, 256, KOUT_SMEM>>>(bout, out);
}